// round 10
// baseline (speedup 1.0000x reference)
#include <cuda_runtime.h>
#include <cuda_bf16.h>
#include <math.h>
#include <stdint.h>

#define BATCH 4096
#define NCLS 1000
#define DIM 512
#define QSZ 8192
#define INV_T (1.0f / 0.07f)
#define EPSP 1e-8f

#define QP_CAP 16384            // padded queue capacity (worst case < 16000)
#define NHALF (QP_CAP / 64)     // 256 half-tiles max
#define MAXCH (NCLS + NHALF + 8)
#define MAXCHP 1280             // row stride for chunk-lse matrix

// ---------------- scratch (__device__ globals; no allocations allowed) ------
__device__ __nv_bfloat16 g_featbf[BATCH * DIM];
__device__ __nv_bfloat16 g_centbf[NCLS * DIM];
__device__ __nv_bfloat16 g_qpbf[(size_t)QP_CAP * DIM];
__device__ float g_CS[(size_t)BATCH * NCLS];
__device__ float g_chlse[(size_t)BATCH * MAXCHP];  // per (row, chunk) logsumexp
__device__ int   g_perm[QP_CAP];                   // padded slot -> queue row (-1 = pad)
__device__ int   g_cls_cnt[NCLS];
__device__ int   g_chstart[NCLS + 1];              // class -> chunk range
__device__ int   g_chpos[MAXCH];                   // chunk -> padded start pos
__device__ int   g_chcnt[MAXCH];                   // chunk -> length
__device__ int   g_hfirst[NHALF + 1];              // half-tile -> first chunk
__device__ int   g_meta[2];                        // [0] = rounded padded total
__device__ double g_acc[2];

// ---------------- row L2 normalize -> bf16 -----------------------------------
__global__ void norm_rows_bf(const float* __restrict__ x, __nv_bfloat16* __restrict__ y) {
    int r = blockIdx.x;
    const float4* xr = (const float4*)(x + (size_t)r * DIM);
    float4 v = xr[threadIdx.x];
    float ss = v.x * v.x + v.y * v.y + v.z * v.z + v.w * v.w;
#pragma unroll
    for (int o = 16; o; o >>= 1) ss += __shfl_down_sync(0xffffffffu, ss, o);
    __shared__ float sh[4];
    if ((threadIdx.x & 31) == 0) sh[threadIdx.x >> 5] = ss;
    __syncthreads();
    float tot = sh[0] + sh[1] + sh[2] + sh[3];
    float inv = 1.0f / fmaxf(sqrtf(tot), 1e-12f);
    __nv_bfloat162 lo = __floats2bfloat162_rn(v.x * inv, v.y * inv);
    __nv_bfloat162 hi = __floats2bfloat162_rn(v.z * inv, v.w * inv);
    __nv_bfloat162* yr = (__nv_bfloat162*)(y + (size_t)r * DIM);
    yr[threadIdx.x * 2 + 0] = lo;
    yr[threadIdx.x * 2 + 1] = hi;
}

// ---------------- counting sort + 64-aligned chunked layout (single block) --
__global__ void build_perm(const int* __restrict__ labels) {
    __shared__ int scnt[NCLS];
    __shared__ int scur[NCLS];
    int tid = threadIdx.x;
    for (int i = tid; i < NCLS; i += 1024) { scnt[i] = 0; scur[i] = 0; }
    for (int i = tid; i < QP_CAP; i += 1024) g_perm[i] = -1;
    if (tid == 0) { g_acc[0] = 0.0; g_acc[1] = 0.0; }
    __syncthreads();
    for (int q = tid; q < QSZ; q += 1024) {
        int l = labels[q];
        if (l >= 0 && l < NCLS) atomicAdd(&scnt[l], 1);
    }
    __syncthreads();
    if (tid == 0) {
        int pos = 0, nch = 0;
        for (int c = 0; c < NCLS; c++) {
            g_chstart[c] = nch;
            g_cls_cnt[c] = scnt[c];
            int rem = scnt[c];
            while (rem > 0) {
                int space = 64 - (pos & 63);
                int take = rem < space ? rem : space;
                g_chpos[nch] = pos;
                g_chcnt[nch] = take;
                nch++;
                pos += take;
                rem -= take;
            }
        }
        g_chstart[NCLS] = nch;
        int rounded = (pos + 127) & ~127;
        g_meta[0] = rounded;
        int nh = rounded / 64;
        int j = 0;
        for (int h = 0; h <= nh; h++) {
            while (j < nch && g_chpos[j] < h * 64) j++;
            g_hfirst[h] = j;
        }
        for (int h = nh + 1; h <= NHALF; h++) g_hfirst[h] = nch;
    }
    __syncthreads();
    for (int q = tid; q < QSZ; q += 1024) {
        int l = labels[q];
        if (l < 0 || l >= NCLS) continue;
        int i = atomicAdd(&scur[l], 1);
        int j = g_chstart[l];
        while (i >= g_chcnt[j]) { i -= g_chcnt[j]; j++; }
        g_perm[g_chpos[j] + i] = q;
    }
}

// ---------------- gather queue rows into padded chunked layout (f32->bf16) --
__global__ void permute_queue_bf(const float* __restrict__ queue) {
    int idx = blockIdx.x * blockDim.x + threadIdx.x;
    int r = idx >> 7, c = idx & 127;
    if (r >= g_meta[0]) return;
    int src = g_perm[r];
    __nv_bfloat162 lo, hi;
    if (src >= 0) {
        float4 v = ((const float4*)queue)[(size_t)src * 128 + c];
        lo = __floats2bfloat162_rn(v.x, v.y);
        hi = __floats2bfloat162_rn(v.z, v.w);
    } else {
        lo = __floats2bfloat162_rn(0.f, 0.f);
        hi = lo;
    }
    __nv_bfloat162* yr = (__nv_bfloat162*)(g_qpbf + (size_t)r * DIM);
    yr[c * 2 + 0] = lo;
    yr[c * 2 + 1] = hi;
}

// ---------------- shared bf16 MMA pieces --------------------------------------
#define TBM 128
#define TBN 128
#define TBK 32
#define KP  (TBK / 2)
#define SSTR 132
#define TS 65   // epilogue tile stride (floats)

__device__ __forceinline__ void mma_bf16(float c[4], const uint32_t a[4], const uint32_t b[2]) {
    asm volatile(
        "mma.sync.aligned.m16n8k16.row.col.f32.bf16.bf16.f32 "
        "{%0,%1,%2,%3}, {%4,%5,%6,%7}, {%8,%9}, {%0,%1,%2,%3};"
        : "+f"(c[0]), "+f"(c[1]), "+f"(c[2]), "+f"(c[3])
        : "r"(a[0]), "r"(a[1]), "r"(a[2]), "r"(a[3]), "r"(b[0]), "r"(b[1]));
}

// ---------------- GEMM1: feat @ queue_p^T with fused chunk logsumexp ---------
__global__ __launch_bounds__(256) void gemm_q(const __nv_bfloat16* __restrict__ A,
                                              const __nv_bfloat16* __restrict__ Bm) {
    __shared__ __align__(16) uint32_t smraw[2 * KP * SSTR * 2];  // 33792 B
    uint32_t (*As)[KP][SSTR] = (uint32_t(*)[KP][SSTR])smraw;
    uint32_t (*Bs)[KP][SSTR] = (uint32_t(*)[KP][SSTR])(smraw + 2 * KP * SSTR);
    float* tile = (float*)smraw;  // 128*65 = 8320 floats <= 8448

    int bx = blockIdx.x, by = blockIdx.y;
    if (bx * TBN >= g_meta[0]) return;   // beyond padded queue
    int tid = threadIdx.x;
    int wid = tid >> 5, lane = tid & 31;
    int g = lane >> 2, t = lane & 3;
    int wm = (wid & 3) * 32;
    int wn = (wid >> 2) * 64;
    int m0 = tid >> 2;
    int ch = tid & 3;

    float acc[2][8][4];
#pragma unroll
    for (int i = 0; i < 2; i++)
#pragma unroll
        for (int j = 0; j < 8; j++)
#pragma unroll
            for (int r = 0; r < 4; r++) acc[i][j][r] = 0.f;

    const __nv_bfloat16* Abase = A + (size_t)(by * TBM) * DIM;
    const __nv_bfloat16* Bbase = Bm + (size_t)(bx * TBN) * DIM;

    uint4 ra0, ra1, rb0, rb1;
    {
        int kc = ch * 8;
        ra0 = *(const uint4*)(Abase + (size_t)m0 * DIM + kc);
        ra1 = *(const uint4*)(Abase + (size_t)(m0 + 64) * DIM + kc);
        rb0 = *(const uint4*)(Bbase + (size_t)m0 * DIM + kc);
        rb1 = *(const uint4*)(Bbase + (size_t)(m0 + 64) * DIM + kc);
    }
    {
        int kp = ch * 4;
        As[0][kp + 0][m0] = ra0.x; As[0][kp + 1][m0] = ra0.y;
        As[0][kp + 2][m0] = ra0.z; As[0][kp + 3][m0] = ra0.w;
        As[0][kp + 0][m0 + 64] = ra1.x; As[0][kp + 1][m0 + 64] = ra1.y;
        As[0][kp + 2][m0 + 64] = ra1.z; As[0][kp + 3][m0 + 64] = ra1.w;
        Bs[0][kp + 0][m0] = rb0.x; Bs[0][kp + 1][m0] = rb0.y;
        Bs[0][kp + 2][m0] = rb0.z; Bs[0][kp + 3][m0] = rb0.w;
        Bs[0][kp + 0][m0 + 64] = rb1.x; Bs[0][kp + 1][m0 + 64] = rb1.y;
        Bs[0][kp + 2][m0 + 64] = rb1.z; Bs[0][kp + 3][m0 + 64] = rb1.w;
    }
    __syncthreads();

    const int ntiles = DIM / TBK;  // 16
    int buf = 0;
    for (int kt = 0; kt < ntiles; kt++) {
        bool more = (kt + 1) < ntiles;
        if (more) {
            int kc = (kt + 1) * TBK + ch * 8;
            ra0 = *(const uint4*)(Abase + (size_t)m0 * DIM + kc);
            ra1 = *(const uint4*)(Abase + (size_t)(m0 + 64) * DIM + kc);
            rb0 = *(const uint4*)(Bbase + (size_t)m0 * DIM + kc);
            rb1 = *(const uint4*)(Bbase + (size_t)(m0 + 64) * DIM + kc);
        }
#pragma unroll
        for (int ks = 0; ks < 2; ks++) {
            int ko = ks * 8;
            uint32_t afr[2][4], bfr[8][2];
#pragma unroll
            for (int i = 0; i < 2; i++) {
                int m = wm + i * 16 + g;
                afr[i][0] = As[buf][ko + t][m];
                afr[i][1] = As[buf][ko + t][m + 8];
                afr[i][2] = As[buf][ko + t + 4][m];
                afr[i][3] = As[buf][ko + t + 4][m + 8];
            }
#pragma unroll
            for (int j = 0; j < 8; j++) {
                int n = wn + j * 8 + g;
                bfr[j][0] = Bs[buf][ko + t][n];
                bfr[j][1] = Bs[buf][ko + t + 4][n];
            }
#pragma unroll
            for (int i = 0; i < 2; i++)
#pragma unroll
                for (int j = 0; j < 8; j++) mma_bf16(acc[i][j], afr[i], bfr[j]);
        }
        if (more) {
            int nb = buf ^ 1;
            int kp = ch * 4;
            As[nb][kp + 0][m0] = ra0.x; As[nb][kp + 1][m0] = ra0.y;
            As[nb][kp + 2][m0] = ra0.z; As[nb][kp + 3][m0] = ra0.w;
            As[nb][kp + 0][m0 + 64] = ra1.x; As[nb][kp + 1][m0 + 64] = ra1.y;
            As[nb][kp + 2][m0 + 64] = ra1.z; As[nb][kp + 3][m0 + 64] = ra1.w;
            Bs[nb][kp + 0][m0] = rb0.x; Bs[nb][kp + 1][m0] = rb0.y;
            Bs[nb][kp + 2][m0] = rb0.z; Bs[nb][kp + 3][m0] = rb0.w;
            Bs[nb][kp + 0][m0 + 64] = rb1.x; Bs[nb][kp + 1][m0 + 64] = rb1.y;
            Bs[nb][kp + 2][m0 + 64] = rb1.z; Bs[nb][kp + 3][m0 + 64] = rb1.w;
            __syncthreads();
            buf = nb;
        }
    }

    // ---- fused epilogue: per-chunk logsumexp over this tile's columns ----
    __syncthreads();   // all fragment reads done; safe to overwrite As/Bs
    int hsel = wid >> 2;   // which 64-col half this warp's accs cover
#pragma unroll
    for (int h = 0; h < 2; h++) {
        if (hsel == h) {
#pragma unroll
            for (int i = 0; i < 2; i++) {
                int r = wm + i * 16 + g;
#pragma unroll
                for (int j = 0; j < 8; j++) {
                    int cl = j * 8 + t * 2;
                    tile[r * TS + cl]           = INV_T * acc[i][j][0];
                    tile[r * TS + cl + 1]       = INV_T * acc[i][j][1];
                    tile[(r + 8) * TS + cl]     = INV_T * acc[i][j][2];
                    tile[(r + 8) * TS + cl + 1] = INV_T * acc[i][j][3];
                }
            }
        }
        __syncthreads();
        int ht = bx * 2 + h;
        int cf = g_hfirst[ht], ce = g_hfirst[ht + 1];
        int r = tid >> 1, par = tid & 1;
        int bg = by * TBM + r;
        const float* trow = tile + r * TS;
        int base = ht * 64;
        for (int cc = cf + par; cc < ce; cc += 2) {
            int p0 = g_chpos[cc] - base, n = g_chcnt[cc];
            float mx = -INFINITY;
            for (int q = 0; q < n; q++) mx = fmaxf(mx, trow[p0 + q]);
            float se = 0.f;
            for (int q = 0; q < n; q++) se += __expf(trow[p0 + q] - mx);
            g_chlse[(size_t)bg * MAXCHP + cc] = mx + __logf(se);
        }
        __syncthreads();
    }
}

// ---------------- GEMM2: feat @ centers^T (generic, writes CS) ---------------
__global__ __launch_bounds__(256) void gemm_bf16(const __nv_bfloat16* __restrict__ A,
                                                 const __nv_bfloat16* __restrict__ Bm,
                                                 float* __restrict__ Cm,
                                                 int N, int K, float alpha) {
    __shared__ uint32_t As[2][KP][SSTR];
    __shared__ uint32_t Bs[2][KP][SSTR];
    int tid = threadIdx.x;
    int bx = blockIdx.x, by = blockIdx.y;
    int wid = tid >> 5, lane = tid & 31;
    int g = lane >> 2, t = lane & 3;
    int wm = (wid & 3) * 32;
    int wn = (wid >> 2) * 64;
    int m0 = tid >> 2;
    int ch = tid & 3;

    float acc[2][8][4];
#pragma unroll
    for (int i = 0; i < 2; i++)
#pragma unroll
        for (int j = 0; j < 8; j++)
#pragma unroll
            for (int r = 0; r < 4; r++) acc[i][j][r] = 0.f;

    const __nv_bfloat16* Abase = A + (size_t)(by * TBM) * K;
    int nrow0 = bx * TBN + m0;
    int nrow1 = nrow0 + 64;
    bool bv0 = nrow0 < N, bv1 = nrow1 < N;

    uint4 ra0, ra1, rb0, rb1;
    {
        int kc = ch * 8;
        ra0 = *(const uint4*)(Abase + (size_t)m0 * K + kc);
        ra1 = *(const uint4*)(Abase + (size_t)(m0 + 64) * K + kc);
        rb0 = bv0 ? *(const uint4*)(Bm + (size_t)nrow0 * K + kc) : make_uint4(0, 0, 0, 0);
        rb1 = bv1 ? *(const uint4*)(Bm + (size_t)nrow1 * K + kc) : make_uint4(0, 0, 0, 0);
    }
    {
        int kp = ch * 4;
        As[0][kp + 0][m0] = ra0.x; As[0][kp + 1][m0] = ra0.y;
        As[0][kp + 2][m0] = ra0.z; As[0][kp + 3][m0] = ra0.w;
        As[0][kp + 0][m0 + 64] = ra1.x; As[0][kp + 1][m0 + 64] = ra1.y;
        As[0][kp + 2][m0 + 64] = ra1.z; As[0][kp + 3][m0 + 64] = ra1.w;
        Bs[0][kp + 0][m0] = rb0.x; Bs[0][kp + 1][m0] = rb0.y;
        Bs[0][kp + 2][m0] = rb0.z; Bs[0][kp + 3][m0] = rb0.w;
        Bs[0][kp + 0][m0 + 64] = rb1.x; Bs[0][kp + 1][m0 + 64] = rb1.y;
        Bs[0][kp + 2][m0 + 64] = rb1.z; Bs[0][kp + 3][m0 + 64] = rb1.w;
    }
    __syncthreads();

    int ntiles = K / TBK;
    int buf = 0;
    for (int kt = 0; kt < ntiles; kt++) {
        bool more = (kt + 1) < ntiles;
        if (more) {
            int kc = (kt + 1) * TBK + ch * 8;
            ra0 = *(const uint4*)(Abase + (size_t)m0 * K + kc);
            ra1 = *(const uint4*)(Abase + (size_t)(m0 + 64) * K + kc);
            rb0 = bv0 ? *(const uint4*)(Bm + (size_t)nrow0 * K + kc) : make_uint4(0, 0, 0, 0);
            rb1 = bv1 ? *(const uint4*)(Bm + (size_t)nrow1 * K + kc) : make_uint4(0, 0, 0, 0);
        }
#pragma unroll
        for (int ks = 0; ks < 2; ks++) {
            int ko = ks * 8;
            uint32_t afr[2][4], bfr[8][2];
#pragma unroll
            for (int i = 0; i < 2; i++) {
                int m = wm + i * 16 + g;
                afr[i][0] = As[buf][ko + t][m];
                afr[i][1] = As[buf][ko + t][m + 8];
                afr[i][2] = As[buf][ko + t + 4][m];
                afr[i][3] = As[buf][ko + t + 4][m + 8];
            }
#pragma unroll
            for (int j = 0; j < 8; j++) {
                int n = wn + j * 8 + g;
                bfr[j][0] = Bs[buf][ko + t][n];
                bfr[j][1] = Bs[buf][ko + t + 4][n];
            }
#pragma unroll
            for (int i = 0; i < 2; i++)
#pragma unroll
                for (int j = 0; j < 8; j++) mma_bf16(acc[i][j], afr[i], bfr[j]);
        }
        if (more) {
            int nb = buf ^ 1;
            int kp = ch * 4;
            As[nb][kp + 0][m0] = ra0.x; As[nb][kp + 1][m0] = ra0.y;
            As[nb][kp + 2][m0] = ra0.z; As[nb][kp + 3][m0] = ra0.w;
            As[nb][kp + 0][m0 + 64] = ra1.x; As[nb][kp + 1][m0 + 64] = ra1.y;
            As[nb][kp + 2][m0 + 64] = ra1.z; As[nb][kp + 3][m0 + 64] = ra1.w;
            Bs[nb][kp + 0][m0] = rb0.x; Bs[nb][kp + 1][m0] = rb0.y;
            Bs[nb][kp + 2][m0] = rb0.z; Bs[nb][kp + 3][m0] = rb0.w;
            Bs[nb][kp + 0][m0 + 64] = rb1.x; Bs[nb][kp + 1][m0 + 64] = rb1.y;
            Bs[nb][kp + 2][m0 + 64] = rb1.z; Bs[nb][kp + 3][m0 + 64] = rb1.w;
            __syncthreads();
            buf = nb;
        }
    }

#pragma unroll
    for (int i = 0; i < 2; i++) {
        int row = by * TBM + wm + i * 16 + g;
#pragma unroll
        for (int j = 0; j < 8; j++) {
            int col = bx * TBN + wn + j * 8 + t * 2;
            if (col + 1 < N) {
                float2 v0 = make_float2(alpha * acc[i][j][0], alpha * acc[i][j][1]);
                float2 v1 = make_float2(alpha * acc[i][j][2], alpha * acc[i][j][3]);
                *(float2*)(Cm + (size_t)row * N + col) = v0;
                *(float2*)(Cm + (size_t)(row + 8) * N + col) = v1;
            } else if (col < N) {
                Cm[(size_t)row * N + col] = alpha * acc[i][j][0];
                Cm[(size_t)(row + 8) * N + col] = alpha * acc[i][j][2];
            }
        }
    }
}

// ---------------- contrastive CE: one block per batch row -------------------
__global__ __launch_bounds__(256) void row_contrastive(const float* __restrict__ prior,
                                                       const int* __restrict__ targets,
                                                       const unsigned char* __restrict__ init) {
    int b = blockIdx.x, tid = threadIdx.x;
    const float* chrow = g_chlse + (size_t)b * MAXCHP;
    const float* CSrow = g_CS + (size_t)b * NCLS;
    int tgt = targets[b];
    __shared__ float sm[256], ssum[256];
    __shared__ float stv;
    float m = -INFINITY, s = 0.f;
    for (int c = tid; c < NCLS; c += 256) {
        int cnt = g_cls_cnt[c];
        float ql = 0.f;
        if (cnt > 0) {
            int c0 = g_chstart[c], c1 = g_chstart[c + 1];
            float l = chrow[c0];
            for (int j = c0 + 1; j < c1; j++) {
                float l2 = chrow[j];
                float a = fmaxf(l, l2), d = fminf(l, l2);
                l = a + log1pf(__expf(d - a));
            }
            ql = l - __logf((float)cnt);
        }
        float cl = init[c] ? CSrow[c] : 0.f;
        float a = fmaxf(cl, ql), d = fminf(cl, ql);
        float comp = a + log1pf(__expf(d - a));
        float v = comp - logf(fmaxf(prior[c], EPSP));
        if (c == tgt) stv = v;
        if (v > m) { s = s * __expf(m - v) + 1.f; m = v; }
        else        { s += __expf(v - m); }
    }
    sm[tid] = m; ssum[tid] = s;
    __syncthreads();
    for (int o = 128; o; o >>= 1) {
        if (tid < o) {
            float m2 = sm[tid + o], s2 = ssum[tid + o];
            float M = fmaxf(sm[tid], m2);
            ssum[tid] = ssum[tid] * __expf(sm[tid] - M) + s2 * __expf(m2 - M);
            sm[tid] = M;
        }
        __syncthreads();
    }
    if (tid == 0) {
        float lse = sm[0] + __logf(ssum[0]);
        atomicAdd(&g_acc[1], (double)(lse - stv));
    }
}

// ---------------- plain classification CE -----------------------------------
__global__ __launch_bounds__(256) void row_cls(const float* __restrict__ logits,
                                               const float* __restrict__ prior,
                                               const int* __restrict__ targets) {
    int b = blockIdx.x, tid = threadIdx.x;
    const float* L = logits + (size_t)b * NCLS;
    int tgt = targets[b];
    __shared__ float sm[256], ssum[256];
    __shared__ float stv;
    float m = -INFINITY, s = 0.f;
    for (int c = tid; c < NCLS; c += 256) {
        float v = L[c] - logf(fmaxf(prior[c], EPSP));
        if (c == tgt) stv = v;
        if (v > m) { s = s * __expf(m - v) + 1.f; m = v; }
        else        { s += __expf(v - m); }
    }
    sm[tid] = m; ssum[tid] = s;
    __syncthreads();
    for (int o = 128; o; o >>= 1) {
        if (tid < o) {
            float m2 = sm[tid + o], s2 = ssum[tid + o];
            float M = fmaxf(sm[tid], m2);
            ssum[tid] = ssum[tid] * __expf(sm[tid] - M) + s2 * __expf(m2 - M);
            sm[tid] = M;
        }
        __syncthreads();
    }
    if (tid == 0) {
        float lse = sm[0] + __logf(ssum[0]);
        atomicAdd(&g_acc[0], (double)(lse - stv));
    }
}

__global__ void finalize(float* out) {
    out[0] = (float)(1.0 * (g_acc[0] / BATCH) + 0.1 * (g_acc[1] / BATCH));
}

// ---------------- launch ----------------------------------------------------
extern "C" void kernel_launch(void* const* d_in, const int* in_sizes, int n_in,
                              void* d_out, int out_size) {
    const float* logits    = (const float*)d_in[0];
    const float* embed     = (const float*)d_in[1];
    const float* centers   = (const float*)d_in[2];
    const float* queue     = (const float*)d_in[3];
    const float* prior     = (const float*)d_in[4];
    const int*   targets   = (const int*)d_in[5];
    const unsigned char* cinit = (const unsigned char*)d_in[6];
    const int*   qlabels   = (const int*)d_in[7];
    float* out = (float*)d_out;

    __nv_bfloat16* featbf; cudaGetSymbolAddress((void**)&featbf, g_featbf);
    __nv_bfloat16* centbf; cudaGetSymbolAddress((void**)&centbf, g_centbf);
    __nv_bfloat16* qpbf;   cudaGetSymbolAddress((void**)&qpbf,   g_qpbf);
    float* CS; cudaGetSymbolAddress((void**)&CS, g_CS);

    norm_rows_bf<<<BATCH, 128>>>(embed, featbf);
    norm_rows_bf<<<NCLS, 128>>>(centers, centbf);
    build_perm<<<1, 1024>>>(qlabels);
    permute_queue_bf<<<(QP_CAP * 128) / 256, 256>>>(queue);

    dim3 gQ(QP_CAP / TBN, BATCH / TBM);        // unused col tiles exit early
    gemm_q<<<gQ, 256>>>(featbf, qpbf);
    dim3 gC((NCLS + TBN - 1) / TBN, BATCH / TBM);
    gemm_bf16<<<gC, 256>>>(featbf, centbf, CS, NCLS, DIM, INV_T);

    row_contrastive<<<BATCH, 256>>>(prior, targets, cinit);
    row_cls<<<BATCH, 256>>>(logits, prior, targets);
    finalize<<<1, 1>>>(out);
}

// round 11
// speedup vs baseline: 1.4262x; 1.4262x over previous
#include <cuda_runtime.h>
#include <cuda_bf16.h>
#include <math.h>
#include <stdint.h>

#define BATCH 4096
#define NCLS 1000
#define DIM 512
#define QSZ 8192
#define INV_T (1.0f / 0.07f)
#define EPSP 1e-8f

// ---------------- scratch (__device__ globals; no allocations allowed) ------
__device__ __nv_bfloat16 g_featbf[BATCH * DIM];   // normalized embeddings (bf16)
__device__ __nv_bfloat16 g_centbf[NCLS * DIM];    // normalized centers (bf16)
__device__ __nv_bfloat16 g_qpbf[QSZ * DIM];       // label-permuted queue (bf16)
__device__ __nv_bfloat16 g_Sbf[(size_t)BATCH * QSZ];  // feat @ queue_p^T / T (bf16)
__device__ float g_CS[(size_t)BATCH * NCLS];      // feat @ cent^T / T
__device__ int   g_start[NCLS + 2];
__device__ int   g_perm[QSZ];
__device__ double g_acc[2];

// ---------------- row L2 normalize -> bf16 -----------------------------------
__global__ void norm_rows_bf(const float* __restrict__ x, __nv_bfloat16* __restrict__ y) {
    int r = blockIdx.x;
    const float4* xr = (const float4*)(x + (size_t)r * DIM);
    float4 v = xr[threadIdx.x];
    float ss = v.x * v.x + v.y * v.y + v.z * v.z + v.w * v.w;
#pragma unroll
    for (int o = 16; o; o >>= 1) ss += __shfl_down_sync(0xffffffffu, ss, o);
    __shared__ float sh[4];
    if ((threadIdx.x & 31) == 0) sh[threadIdx.x >> 5] = ss;
    __syncthreads();
    float tot = sh[0] + sh[1] + sh[2] + sh[3];
    float inv = 1.0f / fmaxf(sqrtf(tot), 1e-12f);
    __nv_bfloat162 lo = __floats2bfloat162_rn(v.x * inv, v.y * inv);
    __nv_bfloat162 hi = __floats2bfloat162_rn(v.z * inv, v.w * inv);
    __nv_bfloat162* yr = (__nv_bfloat162*)(y + (size_t)r * DIM);
    yr[threadIdx.x * 2 + 0] = lo;
    yr[threadIdx.x * 2 + 1] = hi;
}

// ---------------- counting sort of queue labels (single block) --------------
__global__ void build_perm(const int* __restrict__ labels) {
    __shared__ int cnt[NCLS + 1];
    __shared__ int cur[NCLS + 1];
    int tid = threadIdx.x;
    for (int i = tid; i < NCLS + 1; i += blockDim.x) cnt[i] = 0;
    if (tid == 0) { g_acc[0] = 0.0; g_acc[1] = 0.0; }
    __syncthreads();
    for (int q = tid; q < QSZ; q += blockDim.x) {
        int l = labels[q];
        int b = (l >= 0 && l < NCLS) ? l : NCLS;
        atomicAdd(&cnt[b], 1);
    }
    __syncthreads();
    if (tid == 0) {
        int run = 0;
        for (int c = 0; c < NCLS + 1; c++) {
            cur[c] = run;
            g_start[c] = run;
            run += cnt[c];
        }
        g_start[NCLS + 1] = run;
    }
    __syncthreads();
    for (int q = tid; q < QSZ; q += blockDim.x) {
        int l = labels[q];
        int b = (l >= 0 && l < NCLS) ? l : NCLS;
        int p = atomicAdd(&cur[b], 1);
        g_perm[p] = q;
    }
}

// ---------------- gather queue rows into label-sorted order (f32 -> bf16) ---
__global__ void permute_queue_bf(const float* __restrict__ queue) {
    int idx = blockIdx.x * blockDim.x + threadIdx.x;  // QSZ*128
    int r = idx >> 7, c = idx & 127;
    int src = g_perm[r];
    float4 v = ((const float4*)queue)[(size_t)src * 128 + c];
    __nv_bfloat162 lo = __floats2bfloat162_rn(v.x, v.y);
    __nv_bfloat162 hi = __floats2bfloat162_rn(v.z, v.w);
    __nv_bfloat162* yr = (__nv_bfloat162*)(g_qpbf + (size_t)r * DIM);
    yr[c * 2 + 0] = lo;
    yr[c * 2 + 1] = hi;
}

// ---------------- bf16 register tensor-core GEMM -----------------------------
// C[m,n] = alpha * sum_k A[m,k]*B[n,k].  A:[M,K] bf16 rm, B:[N,K] bf16 rm.
// Output: f32 (BF16OUT=0) or bf16 (BF16OUT=1), row-major [M,N].
#define TBM 128
#define TBN 128
#define TBK 32
#define KP  (TBK / 2)
#define SSTR 132

__device__ __forceinline__ void mma_bf16(float c[4], const uint32_t a[4], const uint32_t b[2]) {
    asm volatile(
        "mma.sync.aligned.m16n8k16.row.col.f32.bf16.bf16.f32 "
        "{%0,%1,%2,%3}, {%4,%5,%6,%7}, {%8,%9}, {%0,%1,%2,%3};"
        : "+f"(c[0]), "+f"(c[1]), "+f"(c[2]), "+f"(c[3])
        : "r"(a[0]), "r"(a[1]), "r"(a[2]), "r"(a[3]), "r"(b[0]), "r"(b[1]));
}

template <int BF16OUT>
__global__ __launch_bounds__(256) void gemm_bf16(const __nv_bfloat16* __restrict__ A,
                                                 const __nv_bfloat16* __restrict__ Bm,
                                                 void* __restrict__ Cout,
                                                 int N, int K, float alpha) {
    __shared__ uint32_t As[2][KP][SSTR];
    __shared__ uint32_t Bs[2][KP][SSTR];
    int tid = threadIdx.x;
    int bx = blockIdx.x, by = blockIdx.y;
    int wid = tid >> 5, lane = tid & 31;
    int g = lane >> 2, t = lane & 3;
    int wm = (wid & 3) * 32;
    int wn = (wid >> 2) * 64;
    int m0 = tid >> 2;
    int ch = tid & 3;

    float acc[2][8][4];
#pragma unroll
    for (int i = 0; i < 2; i++)
#pragma unroll
        for (int j = 0; j < 8; j++)
#pragma unroll
            for (int r = 0; r < 4; r++) acc[i][j][r] = 0.f;

    const __nv_bfloat16* Abase = A + (size_t)(by * TBM) * K;
    int nrow0 = bx * TBN + m0;
    int nrow1 = nrow0 + 64;
    bool bv0 = nrow0 < N, bv1 = nrow1 < N;

    uint4 ra0, ra1, rb0, rb1;
    {
        int kc = ch * 8;
        ra0 = *(const uint4*)(Abase + (size_t)m0 * K + kc);
        ra1 = *(const uint4*)(Abase + (size_t)(m0 + 64) * K + kc);
        rb0 = bv0 ? *(const uint4*)(Bm + (size_t)nrow0 * K + kc) : make_uint4(0, 0, 0, 0);
        rb1 = bv1 ? *(const uint4*)(Bm + (size_t)nrow1 * K + kc) : make_uint4(0, 0, 0, 0);
    }
    {
        int kp = ch * 4;
        As[0][kp + 0][m0] = ra0.x; As[0][kp + 1][m0] = ra0.y;
        As[0][kp + 2][m0] = ra0.z; As[0][kp + 3][m0] = ra0.w;
        As[0][kp + 0][m0 + 64] = ra1.x; As[0][kp + 1][m0 + 64] = ra1.y;
        As[0][kp + 2][m0 + 64] = ra1.z; As[0][kp + 3][m0 + 64] = ra1.w;
        Bs[0][kp + 0][m0] = rb0.x; Bs[0][kp + 1][m0] = rb0.y;
        Bs[0][kp + 2][m0] = rb0.z; Bs[0][kp + 3][m0] = rb0.w;
        Bs[0][kp + 0][m0 + 64] = rb1.x; Bs[0][kp + 1][m0 + 64] = rb1.y;
        Bs[0][kp + 2][m0 + 64] = rb1.z; Bs[0][kp + 3][m0 + 64] = rb1.w;
    }
    __syncthreads();

    int ntiles = K / TBK;
    int buf = 0;
    for (int kt = 0; kt < ntiles; kt++) {
        bool more = (kt + 1) < ntiles;
        if (more) {
            int kc = (kt + 1) * TBK + ch * 8;
            ra0 = *(const uint4*)(Abase + (size_t)m0 * K + kc);
            ra1 = *(const uint4*)(Abase + (size_t)(m0 + 64) * K + kc);
            rb0 = bv0 ? *(const uint4*)(Bm + (size_t)nrow0 * K + kc) : make_uint4(0, 0, 0, 0);
            rb1 = bv1 ? *(const uint4*)(Bm + (size_t)nrow1 * K + kc) : make_uint4(0, 0, 0, 0);
        }
#pragma unroll
        for (int ks = 0; ks < 2; ks++) {
            int ko = ks * 8;
            uint32_t afr[2][4], bfr[8][2];
#pragma unroll
            for (int i = 0; i < 2; i++) {
                int m = wm + i * 16 + g;
                afr[i][0] = As[buf][ko + t][m];
                afr[i][1] = As[buf][ko + t][m + 8];
                afr[i][2] = As[buf][ko + t + 4][m];
                afr[i][3] = As[buf][ko + t + 4][m + 8];
            }
#pragma unroll
            for (int j = 0; j < 8; j++) {
                int n = wn + j * 8 + g;
                bfr[j][0] = Bs[buf][ko + t][n];
                bfr[j][1] = Bs[buf][ko + t + 4][n];
            }
#pragma unroll
            for (int i = 0; i < 2; i++)
#pragma unroll
                for (int j = 0; j < 8; j++) mma_bf16(acc[i][j], afr[i], bfr[j]);
        }
        if (more) {
            int nb = buf ^ 1;
            int kp = ch * 4;
            As[nb][kp + 0][m0] = ra0.x; As[nb][kp + 1][m0] = ra0.y;
            As[nb][kp + 2][m0] = ra0.z; As[nb][kp + 3][m0] = ra0.w;
            As[nb][kp + 0][m0 + 64] = ra1.x; As[nb][kp + 1][m0 + 64] = ra1.y;
            As[nb][kp + 2][m0 + 64] = ra1.z; As[nb][kp + 3][m0 + 64] = ra1.w;
            Bs[nb][kp + 0][m0] = rb0.x; Bs[nb][kp + 1][m0] = rb0.y;
            Bs[nb][kp + 2][m0] = rb0.z; Bs[nb][kp + 3][m0] = rb0.w;
            Bs[nb][kp + 0][m0 + 64] = rb1.x; Bs[nb][kp + 1][m0 + 64] = rb1.y;
            Bs[nb][kp + 2][m0 + 64] = rb1.z; Bs[nb][kp + 3][m0 + 64] = rb1.w;
            __syncthreads();
            buf = nb;
        }
    }

#pragma unroll
    for (int i = 0; i < 2; i++) {
        int row = by * TBM + wm + i * 16 + g;
#pragma unroll
        for (int j = 0; j < 8; j++) {
            int col = bx * TBN + wn + j * 8 + t * 2;
            if (BF16OUT) {
                __nv_bfloat16* Cm = (__nv_bfloat16*)Cout;
                if (col + 1 < N) {
                    __nv_bfloat162 v0 = __floats2bfloat162_rn(alpha * acc[i][j][0],
                                                              alpha * acc[i][j][1]);
                    __nv_bfloat162 v1 = __floats2bfloat162_rn(alpha * acc[i][j][2],
                                                              alpha * acc[i][j][3]);
                    *(__nv_bfloat162*)(Cm + (size_t)row * N + col) = v0;
                    *(__nv_bfloat162*)(Cm + (size_t)(row + 8) * N + col) = v1;
                } else if (col < N) {
                    Cm[(size_t)row * N + col] = __float2bfloat16(alpha * acc[i][j][0]);
                    Cm[(size_t)(row + 8) * N + col] = __float2bfloat16(alpha * acc[i][j][2]);
                }
            } else {
                float* Cm = (float*)Cout;
                if (col + 1 < N) {
                    float2 v0 = make_float2(alpha * acc[i][j][0], alpha * acc[i][j][1]);
                    float2 v1 = make_float2(alpha * acc[i][j][2], alpha * acc[i][j][3]);
                    *(float2*)(Cm + (size_t)row * N + col) = v0;
                    *(float2*)(Cm + (size_t)(row + 8) * N + col) = v1;
                } else if (col < N) {
                    Cm[(size_t)row * N + col] = alpha * acc[i][j][0];
                    Cm[(size_t)(row + 8) * N + col] = alpha * acc[i][j][2];
                }
            }
        }
    }
}

// ---------------- contrastive CE: one block per batch row, smem-staged S ----
__global__ __launch_bounds__(256) void row_contrastive(const float* __restrict__ prior,
                                                       const int* __restrict__ targets,
                                                       const unsigned char* __restrict__ init) {
    int b = blockIdx.x, tid = threadIdx.x;
    __shared__ __nv_bfloat16 sS[QSZ];          // 16 KB
    __shared__ float sm[256], ssum[256];
    __shared__ float stv;

    // coalesced stage: 16 KB via uint4 (1024 loads, 4 per thread)
    const uint4* src = (const uint4*)(g_Sbf + (size_t)b * QSZ);
    uint4* dst = (uint4*)sS;
#pragma unroll
    for (int i = 0; i < 4; i++) dst[tid + i * 256] = src[tid + i * 256];

    const float* CSrow = g_CS + (size_t)b * NCLS;
    int tgt = targets[b];
    __syncthreads();

    float m = -INFINITY, s = 0.f;
    for (int c = tid; c < NCLS; c += 256) {
        int s0 = g_start[c], s1 = g_start[c + 1];
        int cnt = s1 - s0;
        float ql = 0.f;
        if (cnt > 0) {
            float mx = -INFINITY;
            for (int q = s0; q < s1; q++) mx = fmaxf(mx, __bfloat162float(sS[q]));
            float se = 0.f;
            for (int q = s0; q < s1; q++) se += __expf(__bfloat162float(sS[q]) - mx);
            ql = mx + __logf(se) - __logf((float)cnt);
        }
        float cl = init[c] ? CSrow[c] : 0.f;
        float a = fmaxf(cl, ql), d = fminf(cl, ql);
        float comp = a + log1pf(__expf(d - a));
        float v = comp - logf(fmaxf(prior[c], EPSP));
        if (c == tgt) stv = v;
        if (v > m) { s = s * __expf(m - v) + 1.f; m = v; }
        else        { s += __expf(v - m); }
    }
    sm[tid] = m; ssum[tid] = s;
    __syncthreads();
    for (int o = 128; o; o >>= 1) {
        if (tid < o) {
            float m2 = sm[tid + o], s2 = ssum[tid + o];
            float M = fmaxf(sm[tid], m2);
            ssum[tid] = ssum[tid] * __expf(sm[tid] - M) + s2 * __expf(m2 - M);
            sm[tid] = M;
        }
        __syncthreads();
    }
    if (tid == 0) {
        float lse = sm[0] + __logf(ssum[0]);
        atomicAdd(&g_acc[1], (double)(lse - stv));
    }
}

// ---------------- plain classification CE -----------------------------------
__global__ __launch_bounds__(256) void row_cls(const float* __restrict__ logits,
                                               const float* __restrict__ prior,
                                               const int* __restrict__ targets) {
    int b = blockIdx.x, tid = threadIdx.x;
    const float* L = logits + (size_t)b * NCLS;
    int tgt = targets[b];
    __shared__ float sm[256], ssum[256];
    __shared__ float stv;
    float m = -INFINITY, s = 0.f;
    for (int c = tid; c < NCLS; c += 256) {
        float v = L[c] - logf(fmaxf(prior[c], EPSP));
        if (c == tgt) stv = v;
        if (v > m) { s = s * __expf(m - v) + 1.f; m = v; }
        else        { s += __expf(v - m); }
    }
    sm[tid] = m; ssum[tid] = s;
    __syncthreads();
    for (int o = 128; o; o >>= 1) {
        if (tid < o) {
            float m2 = sm[tid + o], s2 = ssum[tid + o];
            float M = fmaxf(sm[tid], m2);
            ssum[tid] = ssum[tid] * __expf(sm[tid] - M) + s2 * __expf(m2 - M);
            sm[tid] = M;
        }
        __syncthreads();
    }
    if (tid == 0) {
        float lse = sm[0] + __logf(ssum[0]);
        atomicAdd(&g_acc[0], (double)(lse - stv));
    }
}

__global__ void finalize(float* out) {
    out[0] = (float)(1.0 * (g_acc[0] / BATCH) + 0.1 * (g_acc[1] / BATCH));
}

// ---------------- launch ----------------------------------------------------
extern "C" void kernel_launch(void* const* d_in, const int* in_sizes, int n_in,
                              void* d_out, int out_size) {
    const float* logits    = (const float*)d_in[0];
    const float* embed     = (const float*)d_in[1];
    const float* centers   = (const float*)d_in[2];
    const float* queue     = (const float*)d_in[3];
    const float* prior     = (const float*)d_in[4];
    const int*   targets   = (const int*)d_in[5];
    const unsigned char* cinit = (const unsigned char*)d_in[6];
    const int*   qlabels   = (const int*)d_in[7];
    float* out = (float*)d_out;

    __nv_bfloat16* featbf; cudaGetSymbolAddress((void**)&featbf, g_featbf);
    __nv_bfloat16* centbf; cudaGetSymbolAddress((void**)&centbf, g_centbf);
    __nv_bfloat16* qpbf;   cudaGetSymbolAddress((void**)&qpbf,   g_qpbf);
    __nv_bfloat16* Sbf;    cudaGetSymbolAddress((void**)&Sbf,    g_Sbf);
    float* CS; cudaGetSymbolAddress((void**)&CS, g_CS);

    norm_rows_bf<<<BATCH, 128>>>(embed, featbf);
    norm_rows_bf<<<NCLS, 128>>>(centers, centbf);
    build_perm<<<1, 1024>>>(qlabels);
    permute_queue_bf<<<(QSZ * 128) / 256, 256>>>(queue);

    dim3 gS(QSZ / TBN, BATCH / TBM);
    gemm_bf16<1><<<gS, 256>>>(featbf, qpbf, Sbf, QSZ, DIM, INV_T);
    dim3 gC((NCLS + TBN - 1) / TBN, BATCH / TBM);
    gemm_bf16<0><<<gC, 256>>>(featbf, centbf, CS, NCLS, DIM, INV_T);

    row_contrastive<<<BATCH, 256>>>(prior, targets, cinit);
    row_cls<<<BATCH, 256>>>(logits, prior, targets);
    finalize<<<1, 1>>>(out);
}

// round 12
// speedup vs baseline: 1.7859x; 1.2522x over previous
#include <cuda_runtime.h>
#include <cuda_bf16.h>
#include <math.h>
#include <stdint.h>

#define BATCH 4096
#define NCLS 1000
#define DIM 512
#define QSZ 8192
#define INV_T (1.0f / 0.07f)
#define EPSP 1e-8f

// ---------------- scratch (__device__ globals; no allocations allowed) ------
__device__ __nv_bfloat16 g_featbf[BATCH * DIM];   // normalized embeddings (bf16)
__device__ __nv_bfloat16 g_centbf[NCLS * DIM];    // normalized centers (bf16)
__device__ __nv_bfloat16 g_qpbf[QSZ * DIM];       // label-permuted queue (bf16)
__device__ __nv_bfloat16 g_Sbf[(size_t)BATCH * QSZ];  // feat @ queue_p^T / T (bf16)
__device__ float g_CS[(size_t)BATCH * NCLS];      // feat @ cent^T / T
__device__ int   g_start[NCLS + 2];
__device__ int   g_perm[QSZ];
__device__ double g_acc[2];

// ---------------- row L2 normalize -> bf16 -----------------------------------
__global__ void norm_rows_bf(const float* __restrict__ x, __nv_bfloat16* __restrict__ y) {
    int r = blockIdx.x;
    const float4* xr = (const float4*)(x + (size_t)r * DIM);
    float4 v = xr[threadIdx.x];
    float ss = v.x * v.x + v.y * v.y + v.z * v.z + v.w * v.w;
#pragma unroll
    for (int o = 16; o; o >>= 1) ss += __shfl_down_sync(0xffffffffu, ss, o);
    __shared__ float sh[4];
    if ((threadIdx.x & 31) == 0) sh[threadIdx.x >> 5] = ss;
    __syncthreads();
    float tot = sh[0] + sh[1] + sh[2] + sh[3];
    float inv = 1.0f / fmaxf(sqrtf(tot), 1e-12f);
    __nv_bfloat162 lo = __floats2bfloat162_rn(v.x * inv, v.y * inv);
    __nv_bfloat162 hi = __floats2bfloat162_rn(v.z * inv, v.w * inv);
    __nv_bfloat162* yr = (__nv_bfloat162*)(y + (size_t)r * DIM);
    yr[threadIdx.x * 2 + 0] = lo;
    yr[threadIdx.x * 2 + 1] = hi;
}

// ---------------- counting sort of queue labels (single block) --------------
__global__ void build_perm(const int* __restrict__ labels) {
    __shared__ int cnt[NCLS + 1];
    __shared__ int cur[NCLS + 1];
    int tid = threadIdx.x;
    for (int i = tid; i < NCLS + 1; i += blockDim.x) cnt[i] = 0;
    if (tid == 0) { g_acc[0] = 0.0; g_acc[1] = 0.0; }
    __syncthreads();
    for (int q = tid; q < QSZ; q += blockDim.x) {
        int l = labels[q];
        int b = (l >= 0 && l < NCLS) ? l : NCLS;
        atomicAdd(&cnt[b], 1);
    }
    __syncthreads();
    if (tid == 0) {
        int run = 0;
        for (int c = 0; c < NCLS + 1; c++) {
            cur[c] = run;
            g_start[c] = run;
            run += cnt[c];
        }
        g_start[NCLS + 1] = run;
    }
    __syncthreads();
    for (int q = tid; q < QSZ; q += blockDim.x) {
        int l = labels[q];
        int b = (l >= 0 && l < NCLS) ? l : NCLS;
        int p = atomicAdd(&cur[b], 1);
        g_perm[p] = q;
    }
}

// ---------------- gather queue rows into label-sorted order (f32 -> bf16) ---
__global__ void permute_queue_bf(const float* __restrict__ queue) {
    int idx = blockIdx.x * blockDim.x + threadIdx.x;  // QSZ*128
    int r = idx >> 7, c = idx & 127;
    int src = g_perm[r];
    float4 v = ((const float4*)queue)[(size_t)src * 128 + c];
    __nv_bfloat162 lo = __floats2bfloat162_rn(v.x, v.y);
    __nv_bfloat162 hi = __floats2bfloat162_rn(v.z, v.w);
    __nv_bfloat162* yr = (__nv_bfloat162*)(g_qpbf + (size_t)r * DIM);
    yr[c * 2 + 0] = lo;
    yr[c * 2 + 1] = hi;
}

// ---------------- bf16 register tensor-core GEMM (ldmatrix path) -------------
// C[m,n] = alpha * sum_k A[m,k]*B[n,k].  A:[M,K] bf16 rm, B:[N,K] bf16 rm.
// Output: f32 (BF16OUT=0) or bf16 (BF16OUT=1), row-major [M,N].
// Block 128x128x32, 8 warps (4 along M x 2 along N), warp tile 32x64.
// SMEM tiles: [128 rows][4 x 16B chunks], chunk index swizzled: c ^= (row>>1)&3.
#define TBM 128
#define TBN 128
#define TBK 32

__device__ __forceinline__ uint32_t smem_u32(const void* p) {
    uint32_t a;
    asm("{ .reg .u64 t; cvta.to.shared.u64 t, %1; cvt.u32.u64 %0, t; }"
        : "=r"(a) : "l"(p));
    return a;
}

__device__ __forceinline__ void mma_bf16(float c[4], const uint32_t a[4], const uint32_t b[2]) {
    asm volatile(
        "mma.sync.aligned.m16n8k16.row.col.f32.bf16.bf16.f32 "
        "{%0,%1,%2,%3}, {%4,%5,%6,%7}, {%8,%9}, {%0,%1,%2,%3};"
        : "+f"(c[0]), "+f"(c[1]), "+f"(c[2]), "+f"(c[3])
        : "r"(a[0]), "r"(a[1]), "r"(a[2]), "r"(a[3]), "r"(b[0]), "r"(b[1]));
}

__device__ __forceinline__ void ldsm4(uint32_t& r0, uint32_t& r1, uint32_t& r2, uint32_t& r3,
                                      uint32_t addr) {
    asm volatile("ldmatrix.sync.aligned.m8n8.x4.shared.b16 {%0,%1,%2,%3}, [%4];"
                 : "=r"(r0), "=r"(r1), "=r"(r2), "=r"(r3) : "r"(addr));
}

template <int BF16OUT>
__global__ __launch_bounds__(256, 2) void gemm_bf16(const __nv_bfloat16* __restrict__ A,
                                                    const __nv_bfloat16* __restrict__ Bm,
                                                    void* __restrict__ Cout,
                                                    int N, int K, float alpha) {
    __shared__ __align__(16) uint4 As4[2][TBM][4];   // 16 KB
    __shared__ __align__(16) uint4 Bs4[2][TBN][4];   // 16 KB
    int tid = threadIdx.x;
    int bx = blockIdx.x, by = blockIdx.y;
    int wid = tid >> 5, lane = tid & 31;
    int g = lane >> 2, t = lane & 3;
    int wm = (wid & 3) * 32;       // warp offset along M
    int wn = (wid >> 2) * 64;      // warp offset along N
    int m0 = tid >> 2;             // fill row 0..63
    int ch = tid & 3;              // fill 16B chunk

    // swizzled fill chunk (rows m0 and m0+64 share the same swizzle term)
    int swc = ch ^ ((m0 >> 1) & 3);

    // ldmatrix per-lane invariants
    int l15 = lane & 15, hi = lane >> 4;
    int rowA = wm + l15;                    // + i*16 inside the loop
    int rowB = wn + l15;                    // + jj*16 inside the loop
    uint32_t Abase = smem_u32(As4);
    uint32_t Bbase = smem_u32(Bs4);

    float acc[2][8][4];
#pragma unroll
    for (int i = 0; i < 2; i++)
#pragma unroll
        for (int j = 0; j < 8; j++)
#pragma unroll
            for (int r = 0; r < 4; r++) acc[i][j][r] = 0.f;

    const __nv_bfloat16* Abasep = A + (size_t)(by * TBM) * K;
    int nrow0 = bx * TBN + m0;
    int nrow1 = nrow0 + 64;
    bool bv0 = nrow0 < N, bv1 = nrow1 < N;

    uint4 ra0, ra1, rb0, rb1;
    {
        int kc = ch * 8;
        ra0 = *(const uint4*)(Abasep + (size_t)m0 * K + kc);
        ra1 = *(const uint4*)(Abasep + (size_t)(m0 + 64) * K + kc);
        rb0 = bv0 ? *(const uint4*)(Bm + (size_t)nrow0 * K + kc) : make_uint4(0, 0, 0, 0);
        rb1 = bv1 ? *(const uint4*)(Bm + (size_t)nrow1 * K + kc) : make_uint4(0, 0, 0, 0);
    }
    As4[0][m0][swc] = ra0;
    As4[0][m0 + 64][swc] = ra1;
    Bs4[0][m0][swc] = rb0;
    Bs4[0][m0 + 64][swc] = rb1;
    __syncthreads();

    int ntiles = K / TBK;
    int buf = 0;
    for (int kt = 0; kt < ntiles; kt++) {
        bool more = (kt + 1) < ntiles;
        if (more) {
            int kc = (kt + 1) * TBK + ch * 8;
            ra0 = *(const uint4*)(Abasep + (size_t)m0 * K + kc);
            ra1 = *(const uint4*)(Abasep + (size_t)(m0 + 64) * K + kc);
            rb0 = bv0 ? *(const uint4*)(Bm + (size_t)nrow0 * K + kc) : make_uint4(0, 0, 0, 0);
            rb1 = bv1 ? *(const uint4*)(Bm + (size_t)nrow1 * K + kc) : make_uint4(0, 0, 0, 0);
        }
        uint32_t Ab = Abase + (uint32_t)buf * (TBM * 64);
        uint32_t Bb = Bbase + (uint32_t)buf * (TBN * 64);
#pragma unroll
        for (int ks = 0; ks < 2; ks++) {
            int cb = ks * 2 + hi;   // chunk before swizzle
            uint32_t afr[2][4], bfr[8][2];
#pragma unroll
            for (int i = 0; i < 2; i++) {
                int r = rowA + i * 16;
                int c = cb ^ ((r >> 1) & 3);
                ldsm4(afr[i][0], afr[i][1], afr[i][2], afr[i][3],
                      Ab + (uint32_t)r * 64 + (uint32_t)c * 16);
            }
#pragma unroll
            for (int jj = 0; jj < 4; jj++) {
                int r = rowB + jj * 16;
                int c = cb ^ ((r >> 1) & 3);
                uint32_t q0, q1, q2, q3;
                ldsm4(q0, q1, q2, q3, Bb + (uint32_t)r * 64 + (uint32_t)c * 16);
                bfr[2 * jj][0] = q0;  bfr[2 * jj][1] = q2;
                bfr[2 * jj + 1][0] = q1;  bfr[2 * jj + 1][1] = q3;
            }
#pragma unroll
            for (int i = 0; i < 2; i++)
#pragma unroll
                for (int j = 0; j < 8; j++) mma_bf16(acc[i][j], afr[i], bfr[j]);
        }
        if (more) {
            int nb = buf ^ 1;
            As4[nb][m0][swc] = ra0;
            As4[nb][m0 + 64][swc] = ra1;
            Bs4[nb][m0][swc] = rb0;
            Bs4[nb][m0 + 64][swc] = rb1;
            __syncthreads();
            buf = nb;
        }
    }

#pragma unroll
    for (int i = 0; i < 2; i++) {
        int row = by * TBM + wm + i * 16 + g;
#pragma unroll
        for (int j = 0; j < 8; j++) {
            int col = bx * TBN + wn + j * 8 + t * 2;
            if (BF16OUT) {
                __nv_bfloat16* Cm = (__nv_bfloat16*)Cout;
                if (col + 1 < N) {
                    __nv_bfloat162 v0 = __floats2bfloat162_rn(alpha * acc[i][j][0],
                                                              alpha * acc[i][j][1]);
                    __nv_bfloat162 v1 = __floats2bfloat162_rn(alpha * acc[i][j][2],
                                                              alpha * acc[i][j][3]);
                    *(__nv_bfloat162*)(Cm + (size_t)row * N + col) = v0;
                    *(__nv_bfloat162*)(Cm + (size_t)(row + 8) * N + col) = v1;
                } else if (col < N) {
                    Cm[(size_t)row * N + col] = __float2bfloat16(alpha * acc[i][j][0]);
                    Cm[(size_t)(row + 8) * N + col] = __float2bfloat16(alpha * acc[i][j][2]);
                }
            } else {
                float* Cm = (float*)Cout;
                if (col + 1 < N) {
                    float2 v0 = make_float2(alpha * acc[i][j][0], alpha * acc[i][j][1]);
                    float2 v1 = make_float2(alpha * acc[i][j][2], alpha * acc[i][j][3]);
                    *(float2*)(Cm + (size_t)row * N + col) = v0;
                    *(float2*)(Cm + (size_t)(row + 8) * N + col) = v1;
                } else if (col < N) {
                    Cm[(size_t)row * N + col] = alpha * acc[i][j][0];
                    Cm[(size_t)(row + 8) * N + col] = alpha * acc[i][j][2];
                }
            }
        }
    }
}

// ---------------- contrastive CE: one block per batch row, smem-staged S ----
__global__ __launch_bounds__(256) void row_contrastive(const float* __restrict__ prior,
                                                       const int* __restrict__ targets,
                                                       const unsigned char* __restrict__ init) {
    int b = blockIdx.x, tid = threadIdx.x;
    __shared__ __nv_bfloat16 sS[QSZ];          // 16 KB
    __shared__ float sm[256], ssum[256];
    __shared__ float stv;

    const uint4* src = (const uint4*)(g_Sbf + (size_t)b * QSZ);
    uint4* dst = (uint4*)sS;
#pragma unroll
    for (int i = 0; i < 4; i++) dst[tid + i * 256] = src[tid + i * 256];

    const float* CSrow = g_CS + (size_t)b * NCLS;
    int tgt = targets[b];
    __syncthreads();

    float m = -INFINITY, s = 0.f;
    for (int c = tid; c < NCLS; c += 256) {
        int s0 = g_start[c], s1 = g_start[c + 1];
        int cnt = s1 - s0;
        float ql = 0.f;
        if (cnt > 0) {
            float mx = -INFINITY;
            for (int q = s0; q < s1; q++) mx = fmaxf(mx, __bfloat162float(sS[q]));
            float se = 0.f;
            for (int q = s0; q < s1; q++) se += __expf(__bfloat162float(sS[q]) - mx);
            ql = mx + __logf(se) - __logf((float)cnt);
        }
        float cl = init[c] ? CSrow[c] : 0.f;
        float a = fmaxf(cl, ql), d = fminf(cl, ql);
        float comp = a + log1pf(__expf(d - a));
        float v = comp - logf(fmaxf(prior[c], EPSP));
        if (c == tgt) stv = v;
        if (v > m) { s = s * __expf(m - v) + 1.f; m = v; }
        else        { s += __expf(v - m); }
    }
    sm[tid] = m; ssum[tid] = s;
    __syncthreads();
    for (int o = 128; o; o >>= 1) {
        if (tid < o) {
            float m2 = sm[tid + o], s2 = ssum[tid + o];
            float M = fmaxf(sm[tid], m2);
            ssum[tid] = ssum[tid] * __expf(sm[tid] - M) + s2 * __expf(m2 - M);
            sm[tid] = M;
        }
        __syncthreads();
    }
    if (tid == 0) {
        float lse = sm[0] + __logf(ssum[0]);
        atomicAdd(&g_acc[1], (double)(lse - stv));
    }
}

// ---------------- plain classification CE -----------------------------------
__global__ __launch_bounds__(256) void row_cls(const float* __restrict__ logits,
                                               const float* __restrict__ prior,
                                               const int* __restrict__ targets) {
    int b = blockIdx.x, tid = threadIdx.x;
    const float* L = logits + (size_t)b * NCLS;
    int tgt = targets[b];
    __shared__ float sm[256], ssum[256];
    __shared__ float stv;
    float m = -INFINITY, s = 0.f;
    for (int c = tid; c < NCLS; c += 256) {
        float v = L[c] - logf(fmaxf(prior[c], EPSP));
        if (c == tgt) stv = v;
        if (v > m) { s = s * __expf(m - v) + 1.f; m = v; }
        else        { s += __expf(v - m); }
    }
    sm[tid] = m; ssum[tid] = s;
    __syncthreads();
    for (int o = 128; o; o >>= 1) {
        if (tid < o) {
            float m2 = sm[tid + o], s2 = ssum[tid + o];
            float M = fmaxf(sm[tid], m2);
            ssum[tid] = ssum[tid] * __expf(sm[tid] - M) + s2 * __expf(m2 - M);
            sm[tid] = M;
        }
        __syncthreads();
    }
    if (tid == 0) {
        float lse = sm[0] + __logf(ssum[0]);
        atomicAdd(&g_acc[0], (double)(lse - stv));
    }
}

__global__ void finalize(float* out) {
    out[0] = (float)(1.0 * (g_acc[0] / BATCH) + 0.1 * (g_acc[1] / BATCH));
}

// ---------------- launch ----------------------------------------------------
extern "C" void kernel_launch(void* const* d_in, const int* in_sizes, int n_in,
                              void* d_out, int out_size) {
    const float* logits    = (const float*)d_in[0];
    const float* embed     = (const float*)d_in[1];
    const float* centers   = (const float*)d_in[2];
    const float* queue     = (const float*)d_in[3];
    const float* prior     = (const float*)d_in[4];
    const int*   targets   = (const int*)d_in[5];
    const unsigned char* cinit = (const unsigned char*)d_in[6];
    const int*   qlabels   = (const int*)d_in[7];
    float* out = (float*)d_out;

    __nv_bfloat16* featbf; cudaGetSymbolAddress((void**)&featbf, g_featbf);
    __nv_bfloat16* centbf; cudaGetSymbolAddress((void**)&centbf, g_centbf);
    __nv_bfloat16* qpbf;   cudaGetSymbolAddress((void**)&qpbf,   g_qpbf);
    __nv_bfloat16* Sbf;    cudaGetSymbolAddress((void**)&Sbf,    g_Sbf);
    float* CS; cudaGetSymbolAddress((void**)&CS, g_CS);

    norm_rows_bf<<<BATCH, 128>>>(embed, featbf);
    norm_rows_bf<<<NCLS, 128>>>(centers, centbf);
    build_perm<<<1, 1024>>>(qlabels);
    permute_queue_bf<<<(QSZ * 128) / 256, 256>>>(queue);

    dim3 gS(QSZ / TBN, BATCH / TBM);
    gemm_bf16<1><<<gS, 256>>>(featbf, qpbf, Sbf, QSZ, DIM, INV_T);
    dim3 gC((NCLS + TBN - 1) / TBN, BATCH / TBM);
    gemm_bf16<0><<<gC, 256>>>(featbf, centbf, CS, NCLS, DIM, INV_T);

    row_contrastive<<<BATCH, 256>>>(prior, targets, cinit);
    row_cls<<<BATCH, 256>>>(logits, prior, targets);
    finalize<<<1, 1>>>(out);
}

// round 13
// speedup vs baseline: 1.9527x; 1.0934x over previous
#include <cuda_runtime.h>
#include <cuda_bf16.h>
#include <math.h>
#include <stdint.h>

#define BATCH 4096
#define NCLS 1000
#define DIM 512
#define QSZ 8192
#define INV_T (1.0f / 0.07f)
#define EPSP 1e-8f

// ---------------- scratch (__device__ globals; no allocations allowed) ------
__device__ __nv_bfloat16 g_featbf[BATCH * DIM];   // normalized embeddings (bf16)
__device__ __nv_bfloat16 g_centbf[NCLS * DIM];    // normalized centers (bf16)
__device__ __nv_bfloat16 g_qpbf[QSZ * DIM];       // label-permuted queue (bf16)
__device__ __nv_bfloat16 g_Sbf[(size_t)BATCH * QSZ];  // feat @ queue_p^T / T (bf16)
__device__ float g_CS[(size_t)BATCH * NCLS];      // feat @ cent^T / T
__device__ int   g_start[NCLS + 2];
__device__ int   g_perm[QSZ];
__device__ double g_acc[2];

// ---------------- row L2 normalize -> bf16 -----------------------------------
__global__ void norm_rows_bf(const float* __restrict__ x, __nv_bfloat16* __restrict__ y) {
    int r = blockIdx.x;
    const float4* xr = (const float4*)(x + (size_t)r * DIM);
    float4 v = xr[threadIdx.x];
    float ss = v.x * v.x + v.y * v.y + v.z * v.z + v.w * v.w;
#pragma unroll
    for (int o = 16; o; o >>= 1) ss += __shfl_down_sync(0xffffffffu, ss, o);
    __shared__ float sh[4];
    if ((threadIdx.x & 31) == 0) sh[threadIdx.x >> 5] = ss;
    __syncthreads();
    float tot = sh[0] + sh[1] + sh[2] + sh[3];
    float inv = 1.0f / fmaxf(sqrtf(tot), 1e-12f);
    __nv_bfloat162 lo = __floats2bfloat162_rn(v.x * inv, v.y * inv);
    __nv_bfloat162 hi = __floats2bfloat162_rn(v.z * inv, v.w * inv);
    __nv_bfloat162* yr = (__nv_bfloat162*)(y + (size_t)r * DIM);
    yr[threadIdx.x * 2 + 0] = lo;
    yr[threadIdx.x * 2 + 1] = hi;
}

// ---------------- counting sort of queue labels (single block) --------------
__global__ void build_perm(const int* __restrict__ labels) {
    __shared__ int cnt[NCLS + 1];
    __shared__ int cur[NCLS + 1];
    int tid = threadIdx.x;
    for (int i = tid; i < NCLS + 1; i += blockDim.x) cnt[i] = 0;
    if (tid == 0) { g_acc[0] = 0.0; g_acc[1] = 0.0; }
    __syncthreads();
    for (int q = tid; q < QSZ; q += blockDim.x) {
        int l = labels[q];
        int b = (l >= 0 && l < NCLS) ? l : NCLS;
        atomicAdd(&cnt[b], 1);
    }
    __syncthreads();
    if (tid == 0) {
        int run = 0;
        for (int c = 0; c < NCLS + 1; c++) {
            cur[c] = run;
            g_start[c] = run;
            run += cnt[c];
        }
        g_start[NCLS + 1] = run;
    }
    __syncthreads();
    for (int q = tid; q < QSZ; q += blockDim.x) {
        int l = labels[q];
        int b = (l >= 0 && l < NCLS) ? l : NCLS;
        int p = atomicAdd(&cur[b], 1);
        g_perm[p] = q;
    }
}

// ---------------- gather queue rows into label-sorted order (f32 -> bf16) ---
__global__ void permute_queue_bf(const float* __restrict__ queue) {
    int idx = blockIdx.x * blockDim.x + threadIdx.x;  // QSZ*128
    int r = idx >> 7, c = idx & 127;
    int src = g_perm[r];
    float4 v = ((const float4*)queue)[(size_t)src * 128 + c];
    __nv_bfloat162 lo = __floats2bfloat162_rn(v.x, v.y);
    __nv_bfloat162 hi = __floats2bfloat162_rn(v.z, v.w);
    __nv_bfloat162* yr = (__nv_bfloat162*)(g_qpbf + (size_t)r * DIM);
    yr[c * 2 + 0] = lo;
    yr[c * 2 + 1] = hi;
}

// ---------------- bf16 register tensor-core GEMM (cp.async + ldmatrix) -------
// C[m,n] = alpha * sum_k A[m,k]*B[n,k].  A:[M,K] bf16 rm, B:[N,K] bf16 rm.
// Output: f32 (BF16OUT=0) or bf16 (BF16OUT=1), row-major [M,N].
// Block 128x128x32, 8 warps (4 M x 2 N), 3-stage cp.async pipeline.
// SMEM tiles: [stage][128 rows][4 x 16B chunks], chunk swizzle c ^= (row>>1)&3.
#define TBM 128
#define TBN 128
#define TBK 32
#define NSTG 3
#define STG_BYTES (TBM * 64)   // 8192 per matrix per stage

__device__ __forceinline__ uint32_t smem_u32(const void* p) {
    uint32_t a;
    asm("{ .reg .u64 t; cvta.to.shared.u64 t, %1; cvt.u32.u64 %0, t; }"
        : "=r"(a) : "l"(p));
    return a;
}

__device__ __forceinline__ void mma_bf16(float c[4], const uint32_t a[4], const uint32_t b[2]) {
    asm volatile(
        "mma.sync.aligned.m16n8k16.row.col.f32.bf16.bf16.f32 "
        "{%0,%1,%2,%3}, {%4,%5,%6,%7}, {%8,%9}, {%0,%1,%2,%3};"
        : "+f"(c[0]), "+f"(c[1]), "+f"(c[2]), "+f"(c[3])
        : "r"(a[0]), "r"(a[1]), "r"(a[2]), "r"(a[3]), "r"(b[0]), "r"(b[1]));
}

__device__ __forceinline__ void ldsm4(uint32_t& r0, uint32_t& r1, uint32_t& r2, uint32_t& r3,
                                      uint32_t addr) {
    asm volatile("ldmatrix.sync.aligned.m8n8.x4.shared.b16 {%0,%1,%2,%3}, [%4];"
                 : "=r"(r0), "=r"(r1), "=r"(r2), "=r"(r3) : "r"(addr));
}

__device__ __forceinline__ void cpa16(uint32_t dst, const void* src, bool valid) {
    asm volatile("cp.async.cg.shared.global [%0], [%1], 16, %2;"
                 :: "r"(dst), "l"(src), "r"(valid ? 16 : 0));
}
#define CPA_COMMIT() asm volatile("cp.async.commit_group;" ::: "memory")
#define CPA_WAIT1()  asm volatile("cp.async.wait_group 1;" ::: "memory")

template <int BF16OUT>
__global__ __launch_bounds__(256, 2) void gemm_bf16(const __nv_bfloat16* __restrict__ A,
                                                    const __nv_bfloat16* __restrict__ Bm,
                                                    void* __restrict__ Cout,
                                                    int N, int K, float alpha) {
    __shared__ __align__(16) uint4 As4[NSTG][TBM][4];   // 24 KB
    __shared__ __align__(16) uint4 Bs4[NSTG][TBN][4];   // 24 KB
    int tid = threadIdx.x;
    int bx = blockIdx.x, by = blockIdx.y;
    int wid = tid >> 5, lane = tid & 31;
    int g = lane >> 2, t = lane & 3;
    int wm = (wid & 3) * 32;       // warp offset along M
    int wn = (wid >> 2) * 64;      // warp offset along N
    int m0 = tid >> 2;             // fill row 0..63
    int ch = tid & 3;              // fill 16B chunk

    int swc = ch ^ ((m0 >> 1) & 3);
    uint32_t Abase = smem_u32(As4);
    uint32_t Bbase = smem_u32(Bs4);
    // per-thread smem fill addresses (stage 0)
    uint32_t dA0 = Abase + ((uint32_t)m0 * 4 + swc) * 16;
    uint32_t dA1 = dA0 + 64 * 64;
    uint32_t dB0 = Bbase + ((uint32_t)m0 * 4 + swc) * 16;
    uint32_t dB1 = dB0 + 64 * 64;

    // ldmatrix per-lane invariants
    int l15 = lane & 15, hi = lane >> 4;
    int rowA = wm + l15;
    int rowB = wn + l15;

    float acc[2][8][4];
#pragma unroll
    for (int i = 0; i < 2; i++)
#pragma unroll
        for (int j = 0; j < 8; j++)
#pragma unroll
            for (int r = 0; r < 4; r++) acc[i][j][r] = 0.f;

    const __nv_bfloat16* Abasep = A + (size_t)(by * TBM) * K;
    int nrow0 = bx * TBN + m0;
    int nrow1 = nrow0 + 64;
    bool bv0 = nrow0 < N, bv1 = nrow1 < N;
    const __nv_bfloat16* srcA0 = Abasep + (size_t)m0 * K + ch * 8;
    const __nv_bfloat16* srcA1 = Abasep + (size_t)(m0 + 64) * K + ch * 8;
    const __nv_bfloat16* srcB0 = Bm + (size_t)nrow0 * K + ch * 8;   // guarded by bv0
    const __nv_bfloat16* srcB1 = Bm + (size_t)nrow1 * K + ch * 8;   // guarded by bv1

    int ntiles = K / TBK;

    // prologue: issue stages 0 and 1
#pragma unroll
    for (int s = 0; s < NSTG - 1; s++) {
        uint32_t so = (uint32_t)s * STG_BYTES;
        int kc = s * TBK;
        cpa16(dA0 + so, srcA0 + kc, true);
        cpa16(dA1 + so, srcA1 + kc, true);
        cpa16(dB0 + so, srcB0 + kc, bv0);
        cpa16(dB1 + so, srcB1 + kc, bv1);
        CPA_COMMIT();
    }

    int stg = 0;        // stage holding tile kt
    int wstg = NSTG - 1;  // stage to write next prefetch into
    for (int kt = 0; kt < ntiles; kt++) {
        CPA_WAIT1();          // tile kt resident (this thread's part)
        __syncthreads();      // whole tile visible; all warps done with buf wstg

        // prefetch tile kt+2 into wstg (the buffer consumed at iter kt-1)
        if (kt + NSTG - 1 < ntiles) {
            uint32_t so = (uint32_t)wstg * STG_BYTES;
            int kc = (kt + NSTG - 1) * TBK;
            cpa16(dA0 + so, srcA0 + kc, true);
            cpa16(dA1 + so, srcA1 + kc, true);
            cpa16(dB0 + so, srcB0 + kc, bv0);
            cpa16(dB1 + so, srcB1 + kc, bv1);
        }
        CPA_COMMIT();         // always commit (empty group in tail)

        uint32_t Ab = Abase + (uint32_t)stg * STG_BYTES;
        uint32_t Bb = Bbase + (uint32_t)stg * STG_BYTES;
#pragma unroll
        for (int ks = 0; ks < 2; ks++) {
            int cb = ks * 2 + hi;
            uint32_t afr[2][4], bfr[8][2];
#pragma unroll
            for (int i = 0; i < 2; i++) {
                int r = rowA + i * 16;
                int c = cb ^ ((r >> 1) & 3);
                ldsm4(afr[i][0], afr[i][1], afr[i][2], afr[i][3],
                      Ab + (uint32_t)r * 64 + (uint32_t)c * 16);
            }
#pragma unroll
            for (int jj = 0; jj < 4; jj++) {
                int r = rowB + jj * 16;
                int c = cb ^ ((r >> 1) & 3);
                uint32_t q0, q1, q2, q3;
                ldsm4(q0, q1, q2, q3, Bb + (uint32_t)r * 64 + (uint32_t)c * 16);
                bfr[2 * jj][0] = q0;  bfr[2 * jj][1] = q2;
                bfr[2 * jj + 1][0] = q1;  bfr[2 * jj + 1][1] = q3;
            }
#pragma unroll
            for (int i = 0; i < 2; i++)
#pragma unroll
                for (int j = 0; j < 8; j++) mma_bf16(acc[i][j], afr[i], bfr[j]);
        }
        stg = (stg + 1) % NSTG;
        wstg = (wstg + 1) % NSTG;
    }

#pragma unroll
    for (int i = 0; i < 2; i++) {
        int row = by * TBM + wm + i * 16 + g;
#pragma unroll
        for (int j = 0; j < 8; j++) {
            int col = bx * TBN + wn + j * 8 + t * 2;
            if (BF16OUT) {
                __nv_bfloat16* Cm = (__nv_bfloat16*)Cout;
                if (col + 1 < N) {
                    __nv_bfloat162 v0 = __floats2bfloat162_rn(alpha * acc[i][j][0],
                                                              alpha * acc[i][j][1]);
                    __nv_bfloat162 v1 = __floats2bfloat162_rn(alpha * acc[i][j][2],
                                                              alpha * acc[i][j][3]);
                    *(__nv_bfloat162*)(Cm + (size_t)row * N + col) = v0;
                    *(__nv_bfloat162*)(Cm + (size_t)(row + 8) * N + col) = v1;
                } else if (col < N) {
                    Cm[(size_t)row * N + col] = __float2bfloat16(alpha * acc[i][j][0]);
                    Cm[(size_t)(row + 8) * N + col] = __float2bfloat16(alpha * acc[i][j][2]);
                }
            } else {
                float* Cm = (float*)Cout;
                if (col + 1 < N) {
                    float2 v0 = make_float2(alpha * acc[i][j][0], alpha * acc[i][j][1]);
                    float2 v1 = make_float2(alpha * acc[i][j][2], alpha * acc[i][j][3]);
                    *(float2*)(Cm + (size_t)row * N + col) = v0;
                    *(float2*)(Cm + (size_t)(row + 8) * N + col) = v1;
                } else if (col < N) {
                    Cm[(size_t)row * N + col] = alpha * acc[i][j][0];
                    Cm[(size_t)(row + 8) * N + col] = alpha * acc[i][j][2];
                }
            }
        }
    }
}

// ---------------- contrastive CE: one block per batch row, smem-staged S ----
__global__ __launch_bounds__(256) void row_contrastive(const float* __restrict__ prior,
                                                       const int* __restrict__ targets,
                                                       const unsigned char* __restrict__ init) {
    int b = blockIdx.x, tid = threadIdx.x;
    __shared__ __nv_bfloat16 sS[QSZ];          // 16 KB
    __shared__ float sm[256], ssum[256];
    __shared__ float stv;

    const uint4* src = (const uint4*)(g_Sbf + (size_t)b * QSZ);
    uint4* dst = (uint4*)sS;
#pragma unroll
    for (int i = 0; i < 4; i++) dst[tid + i * 256] = src[tid + i * 256];

    const float* CSrow = g_CS + (size_t)b * NCLS;
    int tgt = targets[b];
    __syncthreads();

    float m = -INFINITY, s = 0.f;
    for (int c = tid; c < NCLS; c += 256) {
        int s0 = g_start[c], s1 = g_start[c + 1];
        int cnt = s1 - s0;
        float ql = 0.f;
        if (cnt > 0) {
            float mx = -INFINITY;
            for (int q = s0; q < s1; q++) mx = fmaxf(mx, __bfloat162float(sS[q]));
            float se = 0.f;
            for (int q = s0; q < s1; q++) se += __expf(__bfloat162float(sS[q]) - mx);
            ql = mx + __logf(se) - __logf((float)cnt);
        }
        float cl = init[c] ? CSrow[c] : 0.f;
        float a = fmaxf(cl, ql), d = fminf(cl, ql);
        float comp = a + log1pf(__expf(d - a));
        float v = comp - logf(fmaxf(prior[c], EPSP));
        if (c == tgt) stv = v;
        if (v > m) { s = s * __expf(m - v) + 1.f; m = v; }
        else        { s += __expf(v - m); }
    }
    sm[tid] = m; ssum[tid] = s;
    __syncthreads();
    for (int o = 128; o; o >>= 1) {
        if (tid < o) {
            float m2 = sm[tid + o], s2 = ssum[tid + o];
            float M = fmaxf(sm[tid], m2);
            ssum[tid] = ssum[tid] * __expf(sm[tid] - M) + s2 * __expf(m2 - M);
            sm[tid] = M;
        }
        __syncthreads();
    }
    if (tid == 0) {
        float lse = sm[0] + __logf(ssum[0]);
        atomicAdd(&g_acc[1], (double)(lse - stv));
    }
}

// ---------------- plain classification CE -----------------------------------
__global__ __launch_bounds__(256) void row_cls(const float* __restrict__ logits,
                                               const float* __restrict__ prior,
                                               const int* __restrict__ targets) {
    int b = blockIdx.x, tid = threadIdx.x;
    const float* L = logits + (size_t)b * NCLS;
    int tgt = targets[b];
    __shared__ float sm[256], ssum[256];
    __shared__ float stv;
    float m = -INFINITY, s = 0.f;
    for (int c = tid; c < NCLS; c += 256) {
        float v = L[c] - logf(fmaxf(prior[c], EPSP));
        if (c == tgt) stv = v;
        if (v > m) { s = s * __expf(m - v) + 1.f; m = v; }
        else        { s += __expf(v - m); }
    }
    sm[tid] = m; ssum[tid] = s;
    __syncthreads();
    for (int o = 128; o; o >>= 1) {
        if (tid < o) {
            float m2 = sm[tid + o], s2 = ssum[tid + o];
            float M = fmaxf(sm[tid], m2);
            ssum[tid] = ssum[tid] * __expf(sm[tid] - M) + s2 * __expf(m2 - M);
            sm[tid] = M;
        }
        __syncthreads();
    }
    if (tid == 0) {
        float lse = sm[0] + __logf(ssum[0]);
        atomicAdd(&g_acc[0], (double)(lse - stv));
    }
}

__global__ void finalize(float* out) {
    out[0] = (float)(1.0 * (g_acc[0] / BATCH) + 0.1 * (g_acc[1] / BATCH));
}

// ---------------- launch ----------------------------------------------------
extern "C" void kernel_launch(void* const* d_in, const int* in_sizes, int n_in,
                              void* d_out, int out_size) {
    const float* logits    = (const float*)d_in[0];
    const float* embed     = (const float*)d_in[1];
    const float* centers   = (const float*)d_in[2];
    const float* queue     = (const float*)d_in[3];
    const float* prior     = (const float*)d_in[4];
    const int*   targets   = (const int*)d_in[5];
    const unsigned char* cinit = (const unsigned char*)d_in[6];
    const int*   qlabels   = (const int*)d_in[7];
    float* out = (float*)d_out;

    __nv_bfloat16* featbf; cudaGetSymbolAddress((void**)&featbf, g_featbf);
    __nv_bfloat16* centbf; cudaGetSymbolAddress((void**)&centbf, g_centbf);
    __nv_bfloat16* qpbf;   cudaGetSymbolAddress((void**)&qpbf,   g_qpbf);
    __nv_bfloat16* Sbf;    cudaGetSymbolAddress((void**)&Sbf,    g_Sbf);
    float* CS; cudaGetSymbolAddress((void**)&CS, g_CS);

    norm_rows_bf<<<BATCH, 128>>>(embed, featbf);
    norm_rows_bf<<<NCLS, 128>>>(centers, centbf);
    build_perm<<<1, 1024>>>(qlabels);
    permute_queue_bf<<<(QSZ * 128) / 256, 256>>>(queue);

    dim3 gS(QSZ / TBN, BATCH / TBM);
    gemm_bf16<1><<<gS, 256>>>(featbf, qpbf, Sbf, QSZ, DIM, INV_T);
    dim3 gC((NCLS + TBN - 1) / TBN, BATCH / TBM);
    gemm_bf16<0><<<gC, 256>>>(featbf, centbf, CS, NCLS, DIM, INV_T);

    row_contrastive<<<BATCH, 256>>>(prior, targets, cinit);
    row_cls<<<BATCH, 256>>>(logits, prior, targets);
    finalize<<<1, 1>>>(out);
}